// round 8
// baseline (speedup 1.0000x reference)
#include <cuda_runtime.h>

// LIF spike neuron scan — float4-vectorized register-double-buffered version.
// Each thread owns 4 adjacent chains. x: [B,S,N] fp32, m0: [B,N] fp32.
// out (fp32): spikes [B,S,N] flattened, then m_final [B,N].
// B=32, S=1024, N=2048.

#define B_DIM 32
#define S_DIM 1024
#define N_DIM 2048
#define DECAY 0.8f
#define THRESH 0.5f
#define U 16            // timesteps per pipeline stage
#define BLK 32          // threads per block (1 warp)

#define N4 (N_DIM / 4)  // float4 columns per row = 512

__device__ __forceinline__ float lif_step(float m, float xv, float* spike) {
    m = DECAY * m + xv;
    const bool fire = (m > THRESH);
    *spike = fire ? 1.0f : 0.0f;
    return fire ? 0.0f : m;
}

__global__ __launch_bounds__(BLK) void lif_scan_kernel(
    const float* __restrict__ x,
    const float* __restrict__ m0,
    float* __restrict__ out)
{
    const int p = blockIdx.x * BLK + threadIdx.x;   // float4-chain index, 0..16383
    const int b  = p >> 9;                          // / N4
    const int n4 = p & (N4 - 1);                    // % N4

    const float4* __restrict__ xp =
        (const float4*)(x + (size_t)b * S_DIM * N_DIM) + n4;
    float4* __restrict__ sp =
        (float4*)(out + (size_t)b * S_DIM * N_DIM) + n4;
    const float4* __restrict__ m0p = (const float4*)m0 + p;
    float4* __restrict__ mfin =
        (float4*)(out + (size_t)B_DIM * S_DIM * N_DIM) + p;

    float4 mv = *m0p;
    float m0v = mv.x, m1v = mv.y, m2v = mv.z, m3v = mv.w;

    float4 a[U], bb[U];

    // Prologue: load stage 0
    #pragma unroll
    for (int k = 0; k < U; k++)
        a[k] = __ldcs(xp + (size_t)k * N4);

    #pragma unroll 1
    for (int t = 0; t < S_DIM; t += 2 * U) {
        // Prefetch stage t+U while computing stage t
        #pragma unroll
        for (int k = 0; k < U; k++)
            bb[k] = __ldcs(xp + (size_t)(t + U + k) * N4);

        #pragma unroll
        for (int k = 0; k < U; k++) {
            float4 s;
            m0v = lif_step(m0v, a[k].x, &s.x);
            m1v = lif_step(m1v, a[k].y, &s.y);
            m2v = lif_step(m2v, a[k].z, &s.z);
            m3v = lif_step(m3v, a[k].w, &s.w);
            __stcs(sp + (size_t)(t + k) * N4, s);
        }

        // Prefetch stage t+2U (guarded) while computing stage t+U
        if (t + 2 * U < S_DIM) {
            #pragma unroll
            for (int k = 0; k < U; k++)
                a[k] = __ldcs(xp + (size_t)(t + 2 * U + k) * N4);
        }

        #pragma unroll
        for (int k = 0; k < U; k++) {
            float4 s;
            m0v = lif_step(m0v, bb[k].x, &s.x);
            m1v = lif_step(m1v, bb[k].y, &s.y);
            m2v = lif_step(m2v, bb[k].z, &s.z);
            m3v = lif_step(m3v, bb[k].w, &s.w);
            __stcs(sp + (size_t)(t + U + k) * N4, s);
        }
    }

    *mfin = make_float4(m0v, m1v, m2v, m3v);
}

extern "C" void kernel_launch(void* const* d_in, const int* in_sizes, int n_in,
                              void* d_out, int out_size)
{
    const float* x  = (const float*)d_in[0];
    const float* m0 = (const float*)d_in[1];
    float* out = (float*)d_out;

    const int total4 = (B_DIM * N_DIM) / 4;   // 16384 float4 chains
    const int blocks = total4 / BLK;          // 512 blocks of 32 threads
    lif_scan_kernel<<<blocks, BLK>>>(x, m0, out);
}

// round 9
// speedup vs baseline: 1.1700x; 1.1700x over previous
#include <cuda_runtime.h>

// LIF spike neuron scan — float2-vectorized, U=32 register-double-buffered.
// Each thread owns 2 adjacent chains. x: [B,S,N] fp32, m0: [B,N] fp32.
// out (fp32): spikes [B,S,N] flattened, then m_final [B,N].
// B=32, S=1024, N=2048.

#define B_DIM 32
#define S_DIM 1024
#define N_DIM 2048
#define DECAY 0.8f
#define THRESH 0.5f
#define U 32            // timesteps per pipeline stage
#define BLK 32          // threads per block (1 warp) -> near-perfect CTA balance

#define N2 (N_DIM / 2)  // float2 columns per row = 1024

__global__ __launch_bounds__(BLK) void lif_scan_kernel(
    const float* __restrict__ x,
    const float* __restrict__ m0,
    float* __restrict__ out)
{
    const int p = blockIdx.x * BLK + threadIdx.x;   // float2-chain index, 0..32767
    const int b  = p >> 10;                         // / N2
    const int n2 = p & (N2 - 1);                    // % N2

    const float2* __restrict__ xp =
        (const float2*)(x + (size_t)b * S_DIM * N_DIM) + n2;
    float2* __restrict__ sp =
        (float2*)(out + (size_t)b * S_DIM * N_DIM) + n2;
    const float2* __restrict__ m0p = (const float2*)m0 + p;
    float2* __restrict__ mfin =
        (float2*)(out + (size_t)B_DIM * S_DIM * N_DIM) + p;

    float2 mv = *m0p;
    float mx = mv.x, my = mv.y;

    float2 a[U], bb[U];

    // Prologue: load stage 0
    #pragma unroll
    for (int k = 0; k < U; k++)
        a[k] = __ldcs(xp + (size_t)k * N2);

    #pragma unroll 1
    for (int t = 0; t < S_DIM; t += 2 * U) {
        // Prefetch stage t+U while computing stage t
        #pragma unroll
        for (int k = 0; k < U; k++)
            bb[k] = __ldcs(xp + (size_t)(t + U + k) * N2);

        #pragma unroll
        for (int k = 0; k < U; k++) {
            mx = DECAY * mx + a[k].x;
            my = DECAY * my + a[k].y;
            const bool fx = (mx > THRESH);
            const bool fy = (my > THRESH);
            __stcs(sp + (size_t)(t + k) * N2,
                   make_float2(fx ? 1.0f : 0.0f, fy ? 1.0f : 0.0f));
            mx = fx ? 0.0f : mx;
            my = fy ? 0.0f : my;
        }

        // Prefetch stage t+2U (guarded) while computing stage t+U
        if (t + 2 * U < S_DIM) {
            #pragma unroll
            for (int k = 0; k < U; k++)
                a[k] = __ldcs(xp + (size_t)(t + 2 * U + k) * N2);
        }

        #pragma unroll
        for (int k = 0; k < U; k++) {
            mx = DECAY * mx + bb[k].x;
            my = DECAY * my + bb[k].y;
            const bool fx = (mx > THRESH);
            const bool fy = (my > THRESH);
            __stcs(sp + (size_t)(t + U + k) * N2,
                   make_float2(fx ? 1.0f : 0.0f, fy ? 1.0f : 0.0f));
            mx = fx ? 0.0f : mx;
            my = fy ? 0.0f : my;
        }
    }

    *mfin = make_float2(mx, my);
}

extern "C" void kernel_launch(void* const* d_in, const int* in_sizes, int n_in,
                              void* d_out, int out_size)
{
    const float* x  = (const float*)d_in[0];
    const float* m0 = (const float*)d_in[1];
    float* out = (float*)d_out;

    const int total2 = (B_DIM * N_DIM) / 2;   // 32768 float2 chains
    const int blocks = total2 / BLK;          // 1024 blocks of 32 threads
    lif_scan_kernel<<<blocks, BLK>>>(x, m0, out);
}

// round 10
// speedup vs baseline: 1.1966x; 1.0227x over previous
#include <cuda_runtime.h>

// LIF spike neuron scan — float2, U=32 load double-buffer + batched store bursts.
// Each thread owns 2 adjacent chains. x: [B,S,N] fp32, m0: [B,N] fp32.
// out (fp32): spikes [B,S,N] flattened, then m_final [B,N].
// B=32, S=1024, N=2048.

#define B_DIM 32
#define S_DIM 1024
#define N_DIM 2048
#define DECAY 0.8f
#define THRESH 0.5f
#define U 32            // timesteps per load stage
#define HB 16           // store-burst length (half stage)
#define BLK 32          // threads per block (1 warp)

#define N2 (N_DIM / 2)  // float2 columns per row = 1024

__global__ __launch_bounds__(BLK) void lif_scan_kernel(
    const float* __restrict__ x,
    const float* __restrict__ m0,
    float* __restrict__ out)
{
    const int p = blockIdx.x * BLK + threadIdx.x;   // float2-chain index, 0..32767
    const int b  = p >> 10;                         // / N2
    const int n2 = p & (N2 - 1);                    // % N2

    const float2* __restrict__ xp =
        (const float2*)(x + (size_t)b * S_DIM * N_DIM) + n2;
    float2* __restrict__ sp =
        (float2*)(out + (size_t)b * S_DIM * N_DIM) + n2;
    const float2* __restrict__ m0p = (const float2*)m0 + p;
    float2* __restrict__ mfin =
        (float2*)(out + (size_t)B_DIM * S_DIM * N_DIM) + p;

    float2 mv = *m0p;
    float mx = mv.x, my = mv.y;

    float2 a[U], bb[U];
    float2 s[HB];   // spike batch: computed first, stored as one burst

    // Compute HB steps from src[off..off+HB) into s[], then burst-store.
    #define LIF_HALF(src, off, tbase)                                          \
        do {                                                                   \
            _Pragma("unroll")                                                  \
            for (int k = 0; k < HB; k++) {                                     \
                mx = DECAY * mx + (src)[(off) + k].x;                          \
                my = DECAY * my + (src)[(off) + k].y;                          \
                const bool fx = (mx > THRESH);                                 \
                const bool fy = (my > THRESH);                                 \
                s[k] = make_float2(fx ? 1.0f : 0.0f, fy ? 1.0f : 0.0f);        \
                mx = fx ? 0.0f : mx;                                           \
                my = fy ? 0.0f : my;                                           \
            }                                                                  \
            _Pragma("unroll")                                                  \
            for (int k = 0; k < HB; k++)                                       \
                __stcs(sp + (size_t)((tbase) + k) * N2, s[k]);                 \
        } while (0)

    // Prologue: load stage 0
    #pragma unroll
    for (int k = 0; k < U; k++)
        a[k] = __ldcs(xp + (size_t)k * N2);

    #pragma unroll 1
    for (int t = 0; t < S_DIM; t += 2 * U) {
        // Prefetch stage t+U while computing stage t
        #pragma unroll
        for (int k = 0; k < U; k++)
            bb[k] = __ldcs(xp + (size_t)(t + U + k) * N2);

        LIF_HALF(a, 0,  t);
        LIF_HALF(a, HB, t + HB);

        // Prefetch stage t+2U (guarded) while computing stage t+U
        if (t + 2 * U < S_DIM) {
            #pragma unroll
            for (int k = 0; k < U; k++)
                a[k] = __ldcs(xp + (size_t)(t + 2 * U + k) * N2);
        }

        LIF_HALF(bb, 0,  t + U);
        LIF_HALF(bb, HB, t + U + HB);
    }

    *mfin = make_float2(mx, my);
}

extern "C" void kernel_launch(void* const* d_in, const int* in_sizes, int n_in,
                              void* d_out, int out_size)
{
    const float* x  = (const float*)d_in[0];
    const float* m0 = (const float*)d_in[1];
    float* out = (float*)d_out;

    const int total2 = (B_DIM * N_DIM) / 2;   // 32768 float2 chains
    const int blocks = total2 / BLK;          // 1024 blocks of 32 threads
    lif_scan_kernel<<<blocks, BLK>>>(x, m0, out);
}